// round 17
// baseline (speedup 1.0000x reference)
#include <cuda_runtime.h>
#include <cuda_fp16.h>
#include <cstdint>
#include <math.h>

#define BB 32
#define LC 1024
#define LQ 128
#define DD 256
#define STRB 272                 // 128-col fp16 tile row stride (256B + 16 pad)
#define STRB2 144                // 64-col fp16 tile row stride (128B + 16 pad)
#define AT64  (64 * STRB)        // 17408 B : 64-row x 128-col tile
#define BT128 (128 * STRB)       // 34816 B : 128-row x 128-col tile
#define BT64d (128 * STRB2)      // 18432 B : 128-row x 64-col tile
#define K1PAIR (AT64 + BT128)    // 52224
#define K2PAIR (BT128 + BT64d)   // 53248
#define SM_K1 (2 * K1PAIR + 2816)
#define SM_K2 (2 * K2PAIR)
#define EPH2 72                  // k3 epilogue fp16 staging row stride (halves, 64 cols + pad)
#define EPSZ (64 * EPH2 * 2)     // 9216
#define SM_K3 (2 * BT64d + AT64 + EPSZ)   // 18432*2 + 17408 + 9216 = 63488 -> 3 CTA/SM

// ---------------- scratch ----------------
__device__ float g_Tp[(size_t)BB * 2 * LQ * DD];     // k2 split-K partials (fp32)
__device__ float g_cdot[BB * LC];
__device__ float g_qdotb[BB * LQ];
__device__ float g_rowinv[BB * LC];
__device__ float g_colpart[BB * 16 * LQ];
__device__ int   g_cnt[BB * 4];
__device__ __half g_eh[(size_t)BB * LC * LQ];        // E
__device__ __half g_cbh[(size_t)BB * LC * DD];       // raw C (k1 A, k2 B)
__device__ __half g_qh[(size_t)BB * LQ * DD];        // raw Q (k3 Bq)
__device__ __half g_qwh[(size_t)BB * LQ * DD];       // w3*Q (k1 B)
__device__ __half g_th[(size_t)BB * LQ * DD];        // T

// ---------------- helpers ----------------
__device__ __forceinline__ uint32_t smem_u32(const void* p) {
    uint32_t a;
    asm("{ .reg .u64 t; cvta.to.shared.u64 t, %1; cvt.u32.u64 %0, t; }" : "=r"(a) : "l"(p));
    return a;
}
__device__ __forceinline__ void ldsm4(uint32_t a, uint32_t* r) {
    asm volatile("ldmatrix.sync.aligned.m8n8.x4.shared.b16 {%0,%1,%2,%3}, [%4];"
                 : "=r"(r[0]), "=r"(r[1]), "=r"(r[2]), "=r"(r[3]) : "r"(a));
}
__device__ __forceinline__ void ldsm4t(uint32_t a, uint32_t* r) {
    asm volatile("ldmatrix.sync.aligned.m8n8.x4.trans.shared.b16 {%0,%1,%2,%3}, [%4];"
                 : "=r"(r[0]), "=r"(r[1]), "=r"(r[2]), "=r"(r[3]) : "r"(a));
}
__device__ __forceinline__ void mmah(float* c, const uint32_t* a, const uint32_t* b) {
    asm volatile(
        "mma.sync.aligned.m16n8k16.row.col.f32.f16.f16.f32 "
        "{%0,%1,%2,%3}, {%4,%5,%6,%7}, {%8,%9}, {%0,%1,%2,%3};"
        : "+f"(c[0]), "+f"(c[1]), "+f"(c[2]), "+f"(c[3])
        : "r"(a[0]), "r"(a[1]), "r"(a[2]), "r"(a[3]), "r"(b[0]), "r"(b[1]));
}
__device__ __forceinline__ uint32_t h2pk(float a, float b) {
    __half2 t;
    t.x = __float2half_rn(a);
    t.y = __float2half_rn(b);
    return *(uint32_t*)&t;
}
__device__ __forceinline__ void cpa16(uint32_t dst, const void* src) {
    asm volatile("cp.async.cg.shared.global [%0], [%1], 16;" :: "r"(dst), "l"(src));
}
__device__ __forceinline__ void cpa16z(uint32_t dst, const void* src, uint32_t ssize) {
    asm volatile("cp.async.cg.shared.global [%0], [%1], 16, %2;" :: "r"(dst), "l"(src), "r"(ssize));
}
#define CP_COMMIT() asm volatile("cp.async.commit_group;" ::: "memory")
#define CP_WAIT(n) asm volatile("cp.async.wait_group %0;" :: "n"(n) : "memory")

// ---------------- merged prep: C rows + Q rows (+ counter reset) ----------------
__global__ void k_prep(const float* __restrict__ C, const float* __restrict__ Q,
                       const float* __restrict__ Ww, const float* __restrict__ Wb) {
    if (blockIdx.x == 0 && threadIdx.x < BB * 4) g_cnt[threadIdx.x] = 0;
    int warp = blockIdx.x * 8 + (threadIdx.x >> 5);
    int lane = threadIdx.x & 31;
    int d0 = lane * 4;
    if (warp < BB * LC) {
        const float* row = C + (size_t)warp * DD;
        float4 v1 = *(const float4*)(row + d0);
        float4 v2 = *(const float4*)(row + 128 + d0);
        float4 w1a = *(const float4*)(Ww + d0);
        float4 w1b = *(const float4*)(Ww + 128 + d0);
        float s = v1.x * w1a.x + v1.y * w1a.y + v1.z * w1a.z + v1.w * w1a.w
                + v2.x * w1b.x + v2.y * w1b.y + v2.z * w1b.z + v2.w * w1b.w;
#pragma unroll
        for (int o = 16; o; o >>= 1) s += __shfl_xor_sync(0xFFFFFFFFu, s, o);
        if (lane == 0) g_cdot[warp] = s;
        uint2 u;
        u.x = h2pk(v1.x, v1.y); u.y = h2pk(v1.z, v1.w);
        *(uint2*)(g_cbh + (size_t)warp * DD + d0) = u;
        u.x = h2pk(v2.x, v2.y); u.y = h2pk(v2.z, v2.w);
        *(uint2*)(g_cbh + (size_t)warp * DD + 128 + d0) = u;
    } else {
        int r = warp - BB * LC;
        const float* row = Q + (size_t)r * DD;
        float4 v1 = *(const float4*)(row + d0);
        float4 v2 = *(const float4*)(row + 128 + d0);
        float4 w2a = *(const float4*)(Ww + DD + d0);
        float4 w2b = *(const float4*)(Ww + DD + 128 + d0);
        float s = v1.x * w2a.x + v1.y * w2a.y + v1.z * w2a.z + v1.w * w2a.w
                + v2.x * w2b.x + v2.y * w2b.y + v2.z * w2b.z + v2.w * w2b.w;
#pragma unroll
        for (int o = 16; o; o >>= 1) s += __shfl_xor_sync(0xFFFFFFFFu, s, o);
        if (lane == 0) g_qdotb[r] = s + Wb[0];
        uint2 u;
        u.x = h2pk(v1.x, v1.y); u.y = h2pk(v1.z, v1.w);
        *(uint2*)(g_qh + (size_t)r * DD + d0) = u;
        u.x = h2pk(v2.x, v2.y); u.y = h2pk(v2.z, v2.w);
        *(uint2*)(g_qh + (size_t)r * DD + 128 + d0) = u;
        float4 w3a = *(const float4*)(Ww + 2 * DD + d0);
        float4 w3b = *(const float4*)(Ww + 2 * DD + 128 + d0);
        u.x = h2pk(v1.x * w3a.x, v1.y * w3a.y); u.y = h2pk(v1.z * w3a.z, v1.w * w3a.w);
        *(uint2*)(g_qwh + (size_t)r * DD + d0) = u;
        u.x = h2pk(v2.x * w3b.x, v2.y * w3b.y); u.y = h2pk(v2.z * w3b.z, v2.w * w3b.w);
        *(uint2*)(g_qwh + (size_t)r * DD + 128 + d0) = u;
    }
}

// ---------------- k1: 64c x 128q tiles, 256 thr, 2 CTA/SM ----------------
__global__ __launch_bounds__(256, 2) void k1_mma(const int* __restrict__ cmask,
                                                 const int* __restrict__ qmask) {
    extern __shared__ char sm[];
    const uint32_t smb = smem_u32(sm);
    float* qmf = (float*)(sm + 2 * K1PAIR);
    float* cmf = qmf + 128;
    float* rs = cmf + 64;
    float* cs = rs + 256;
    const int tid = threadIdx.x, lane = tid & 31, wid = tid >> 5;
    const int wm = wid & 1, wn = wid >> 1;
    const int b = blockIdx.y, ct = blockIdx.x, c0 = ct * 64;
    const int g = lane >> 2, tig = lane & 3;

    if (tid < 128) qmf[tid] = (float)qmask[b * LQ + tid];
    else if (tid < 192) cmf[tid - 128] = (float)cmask[b * LC + c0 + tid - 128];

    auto stage = [&](int kc, int bf) {
        uint32_t sa = smb + bf * K1PAIR, sb = sa + AT64;
        const __half* Ag = g_cbh + ((size_t)(b * LC + c0)) * DD + kc * 128;
        const __half* Bg = g_qwh + ((size_t)b * LQ) * DD + kc * 128;
#pragma unroll
        for (int i = 0; i < 4; i++) {
            int idx = i * 256 + tid, row = idx >> 4, cq = idx & 15;
            cpa16(sa + row * STRB + cq * 16, Ag + (size_t)row * DD + cq * 8);
        }
#pragma unroll
        for (int i = 0; i < 8; i++) {
            int idx = i * 256 + tid, row = idx >> 4, cq = idx & 15;
            cpa16(sb + row * STRB + cq * 16, Bg + (size_t)row * DD + cq * 8);
        }
        CP_COMMIT();
    };

    float acc[2][4][4];
#pragma unroll
    for (int i = 0; i < 2; i++)
#pragma unroll
        for (int j = 0; j < 4; j++)
#pragma unroll
            for (int k = 0; k < 4; k++) acc[i][j][k] = 0.f;

    stage(0, 0);
    stage(1, 1);
#pragma unroll
    for (int kc = 0; kc < 2; kc++) {
        if (kc == 0) CP_WAIT(1); else CP_WAIT(0);
        __syncthreads();
        uint32_t sA = smb + (kc & 1) * K1PAIR, sB = sA + AT64;
#pragma unroll
        for (int ks = 0; ks < 8; ks++) {
            uint32_t ah[2][4], bh[4][2];
            uint32_t aro = (uint32_t)(lane & 15) * STRB + (ks * 16 + (lane >> 4) * 8) * 2;
#pragma unroll
            for (int mf = 0; mf < 2; mf++)
                ldsm4(sA + (uint32_t)(wm * 32 + mf * 16) * STRB + aro, ah[mf]);
            uint32_t bro = (uint32_t)((lane & 7) + ((lane >> 4) * 8)) * STRB +
                           (ks * 16 + ((lane >> 3) & 1) * 8) * 2;
#pragma unroll
            for (int np = 0; np < 2; np++) {
                uint32_t r4[4];
                ldsm4(sB + (uint32_t)(wn * 32 + np * 16) * STRB + bro, r4);
                bh[np * 2][0] = r4[0]; bh[np * 2][1] = r4[1];
                bh[np * 2 + 1][0] = r4[2]; bh[np * 2 + 1][1] = r4[3];
            }
#pragma unroll
            for (int mf = 0; mf < 2; mf++)
#pragma unroll
                for (int nf = 0; nf < 4; nf++) mmah(acc[mf][nf], ah[mf], bh[nf]);
        }
    }

    float rpart[2][2] = {{0.f, 0.f}, {0.f, 0.f}};
    float cpart[4][2] = {{0.f, 0.f}, {0.f, 0.f}, {0.f, 0.f}, {0.f, 0.f}};
#pragma unroll
    for (int mf = 0; mf < 2; mf++) {
        int c = c0 + wm * 32 + mf * 16 + g;
        float cd0 = g_cdot[b * LC + c], cd1 = g_cdot[b * LC + c + 8];
        float cm0 = cmf[c - c0], cm1 = cmf[c - c0 + 8];
        size_t r0 = ((size_t)b * LC + c) * LQ, r1 = r0 + 8 * LQ;
#pragma unroll
        for (int nf = 0; nf < 4; nf++) {
            int q = wn * 32 + nf * 8 + tig * 2;
            float qd0 = g_qdotb[b * LQ + q], qd1 = g_qdotb[b * LQ + q + 1];
            float e00 = expf(acc[mf][nf][0] + cd0 + qd0);
            float e01 = expf(acc[mf][nf][1] + cd0 + qd1);
            float e10 = expf(acc[mf][nf][2] + cd1 + qd0);
            float e11 = expf(acc[mf][nf][3] + cd1 + qd1);
            *(uint32_t*)(g_eh + r0 + q) = h2pk(e00, e01);
            *(uint32_t*)(g_eh + r1 + q) = h2pk(e10, e11);
            float qm0 = qmf[q], qm1 = qmf[q + 1];
            rpart[mf][0] += e00 * qm0 + e01 * qm1;
            rpart[mf][1] += e10 * qm0 + e11 * qm1;
            cpart[nf][0] += e00 * cm0 + e10 * cm1;
            cpart[nf][1] += e01 * cm0 + e11 * cm1;
        }
    }
#pragma unroll
    for (int mf = 0; mf < 2; mf++)
#pragma unroll
        for (int rh = 0; rh < 2; rh++) {
            float v = rpart[mf][rh];
            v += __shfl_xor_sync(0xFFFFFFFFu, v, 1);
            v += __shfl_xor_sync(0xFFFFFFFFu, v, 2);
            if (tig == 0) rs[wn * 64 + wm * 32 + mf * 16 + g + rh * 8] = v;
        }
#pragma unroll
    for (int nf = 0; nf < 4; nf++)
#pragma unroll
        for (int j = 0; j < 2; j++) {
            float v = cpart[nf][j];
            v += __shfl_xor_sync(0xFFFFFFFFu, v, 4);
            v += __shfl_xor_sync(0xFFFFFFFFu, v, 8);
            v += __shfl_xor_sync(0xFFFFFFFFu, v, 16);
            if (lane < 4) cs[wid * 32 + nf * 8 + lane * 2 + j] = v;
        }
    __syncthreads();
    if (tid < 64) {
        float s = rs[tid] + rs[64 + tid] + rs[128 + tid] + rs[192 + tid];
        g_rowinv[b * LC + c0 + tid] = 1.f / s;
    } else if (tid < 192) {
        int q = tid - 64, wnq = q >> 5, ql = q & 31;
        float s = cs[(wnq * 2 + 0) * 32 + ql] + cs[(wnq * 2 + 1) * 32 + ql];
        g_colpart[(b * 16 + ct) * LQ + q] = s;
    }
}

// ---------------- k2: 128q x 64d tiles, 256 thr, 2 CTA/SM; last-block reduce -> g_th ------
__global__ __launch_bounds__(256, 2) void k2_mma(const int* __restrict__ cmask) {
    extern __shared__ char sm[];
    const uint32_t smb = smem_u32(sm);
    __shared__ int isLast;
    const int tid = threadIdx.x, lane = tid & 31, wid = tid >> 5;
    const int wm = wid & 3, wn = wid >> 2;
    const int b = blockIdx.y;
    const int dt = blockIdx.x & 3, ksp = blockIdx.x >> 2;
    const int d0 = dt * 64;
    const int g = lane >> 2, tig = lane & 3;

    auto stage = [&](int kc, int bf) {
        uint32_t sa = smb + bf * K2PAIR, sb = sa + BT128;
        int cb = ksp * 512 + kc * 128;
        const __half* Ag = g_eh + ((size_t)(b * LC + cb)) * LQ;
        const __half* Bg = g_cbh + ((size_t)(b * LC + cb)) * DD + d0;
        const int* cm = cmask + b * LC + cb;
#pragma unroll
        for (int i = 0; i < 8; i++) {
            int idx = i * 256 + tid, row = idx >> 4, cq = idx & 15;
            uint32_t ss = cm[row] ? 16u : 0u;
            cpa16z(sa + row * STRB + cq * 16, Ag + (size_t)row * LQ + cq * 8, ss);
        }
#pragma unroll
        for (int i = 0; i < 4; i++) {
            int idx = i * 256 + tid, row = idx >> 3, cq = idx & 7;
            cpa16(sb + row * STRB2 + cq * 16, Bg + (size_t)row * DD + cq * 8);
        }
        CP_COMMIT();
    };

    float acc[2][4][4];
#pragma unroll
    for (int i = 0; i < 2; i++)
#pragma unroll
        for (int j = 0; j < 4; j++)
#pragma unroll
            for (int k = 0; k < 4; k++) acc[i][j][k] = 0.f;

    stage(0, 0);
    for (int kc = 0; kc < 4; kc++) {
        if (kc + 1 < 4) {
            stage(kc + 1, (kc + 1) & 1);
            CP_WAIT(1);
        } else {
            CP_WAIT(0);
        }
        __syncthreads();
        uint32_t sA = smb + (kc & 1) * K2PAIR, sB = sA + BT128;
#pragma unroll
        for (int ks = 0; ks < 8; ks++) {
            uint32_t ah[2][4], bh[4][2];
            uint32_t aro = (uint32_t)(ks * 16 + ((lane >> 4) * 8) + (lane & 7)) * STRB +
                           (((lane >> 3) & 1) * 8) * 2;
#pragma unroll
            for (int mf = 0; mf < 2; mf++)
                ldsm4t(sA + aro + (uint32_t)(wm * 32 + mf * 16) * 2, ah[mf]);
            uint32_t bro = (uint32_t)(ks * 16 + (lane & 15)) * STRB2 + ((lane >> 4) * 8) * 2;
#pragma unroll
            for (int np = 0; np < 2; np++) {
                uint32_t r4[4];
                ldsm4t(sB + bro + (uint32_t)(wn * 32 + np * 16) * 2, r4);
                bh[np * 2][0] = r4[0]; bh[np * 2][1] = r4[1];
                bh[np * 2 + 1][0] = r4[2]; bh[np * 2 + 1][1] = r4[3];
            }
#pragma unroll
            for (int mf = 0; mf < 2; mf++)
#pragma unroll
                for (int nf = 0; nf < 4; nf++) mmah(acc[mf][nf], ah[mf], bh[nf]);
        }
        __syncthreads();
    }
    float* Tp = g_Tp + ((size_t)(b * 2 + ksp) * LQ) * DD;
#pragma unroll
    for (int mf = 0; mf < 2; mf++) {
        int q = wm * 32 + mf * 16 + g;
#pragma unroll
        for (int nf = 0; nf < 4; nf++) {
            int d = d0 + wn * 32 + nf * 8 + tig * 2;
            *(float2*)(Tp + (size_t)q * DD + d) = make_float2(acc[mf][nf][0], acc[mf][nf][1]);
            *(float2*)(Tp + (size_t)(q + 8) * DD + d) = make_float2(acc[mf][nf][2], acc[mf][nf][3]);
        }
    }

    __threadfence();
    if (tid == 0) {
        int old = atomicAdd(&g_cnt[b * 4 + dt], 1);
        isLast = (old == 1);
    }
    __syncthreads();
    if (isLast) {
        float* civ = (float*)sm;
        if (tid < 128) {
            float s = 0.f;
#pragma unroll
            for (int j = 0; j < 16; j++) s += g_colpart[(b * 16 + j) * LQ + tid];
            civ[tid] = 1.f / s;
        }
        __syncthreads();
        const float* P0 = g_Tp + ((size_t)(b * 2 + 0) * LQ) * DD + d0;
        const float* P1 = g_Tp + ((size_t)(b * 2 + 1) * LQ) * DD + d0;
        __half* To = g_th + (size_t)b * LQ * DD + d0;
        for (int i = tid; i < 128 * 16; i += 256) {
            int q = i >> 4, c4 = (i & 15) * 4;
            float4 x0 = __ldcs((const float4*)(P0 + (size_t)q * DD + c4));
            float4 x1 = __ldcs((const float4*)(P1 + (size_t)q * DD + c4));
            float ci = civ[q];
            uint2 u;
            u.x = h2pk((x0.x + x1.x) * ci, (x0.y + x1.y) * ci);
            u.y = h2pk((x0.z + x1.z) * ci, (x0.w + x1.w) * ci);
            *(uint2*)(To + (size_t)q * DD + c4) = u;
        }
    }
}

// ---------------- k3: 64c x 64d tiles, 3 CTA/SM; B-resident over 4 c-tiles ----------------
// grid 512: b = bx>>4, dt = (bx>>2)&3, ctg = bx&3 -> ct in [ctg*4, ctg*4+4)
__global__ __launch_bounds__(256, 3) void k3_mma(const float* __restrict__ Cp,
                                                 const int* __restrict__ qmask,
                                                 float* __restrict__ out) {
    extern __shared__ char sm[];
    const uint32_t smb = smem_u32(sm);
    const uint32_t sBq = smb, sBt = smb + BT64d, sE = smb + 2 * BT64d;
    char* epA = sm + 2 * BT64d;                    // reuses E region (fp16 64 x EPH2)
    char* epB = sm + 2 * BT64d + AT64;             // annex (fp16 64 x EPH2)
    const int tid = threadIdx.x, lane = tid & 31, wid = tid >> 5;
    const int wm = wid & 1, wn = wid >> 1;         // wm: 2 x 32 rows, wn: 4 x 16 cols
    const int bx = blockIdx.x;
    const int b = bx >> 4, dt = (bx >> 2) & 3, ctg = bx & 3;
    const int d0 = dt * 64;
    const int g = lane >> 2, tig = lane & 3;

    auto stageE = [&](int ct) {
        const __half* Ag = g_eh + ((size_t)(b * LC + ct * 64)) * LQ;
#pragma unroll
        for (int i = 0; i < 4; i++) {
            int idx = i * 256 + tid, row = idx >> 4, cq = idx & 15;
            cpa16(sE + row * STRB + cq * 16, Ag + (size_t)row * LQ + cq * 8);
        }
        CP_COMMIT();
    };

    // stage Bq/Bt (128q x 64d, qmask-zeroed rows) + first E tile
    {
        const __half* Bqg = g_qh + ((size_t)b * LQ) * DD + d0;
        const __half* Btg = g_th + ((size_t)b * LQ) * DD + d0;
        const int* qm = qmask + b * LQ;
#pragma unroll
        for (int i = 0; i < 4; i++) {
            int idx = i * 256 + tid, row = idx >> 3, cq = idx & 7;
            uint32_t ss = qm[row] ? 16u : 0u;
            cpa16z(sBq + row * STRB2 + cq * 16, Bqg + (size_t)row * DD + cq * 8, ss);
            cpa16z(sBt + row * STRB2 + cq * 16, Btg + (size_t)row * DD + cq * 8, ss);
        }
        CP_COMMIT();
        stageE(ctg * 4);
    }

    for (int t = 0; t < 4; t++) {
        const int ct = ctg * 4 + t, c0 = ct * 64;
        CP_WAIT(0);
        __syncthreads();

        float accA[2][2][4], accB[2][2][4];
#pragma unroll
        for (int i = 0; i < 2; i++)
#pragma unroll
            for (int j = 0; j < 2; j++)
#pragma unroll
                for (int k = 0; k < 4; k++) { accA[i][j][k] = 0.f; accB[i][j][k] = 0.f; }

#pragma unroll
        for (int ks = 0; ks < 8; ks++) {
            uint32_t ah[2][4], bq[2][2], bt[2][2];
            uint32_t aro = (uint32_t)(lane & 15) * STRB + (ks * 16 + (lane >> 4) * 8) * 2;
#pragma unroll
            for (int mf = 0; mf < 2; mf++)
                ldsm4(sE + (uint32_t)(wm * 32 + mf * 16) * STRB + aro, ah[mf]);
            uint32_t bro = (uint32_t)(ks * 16 + (lane & 15)) * STRB2 + ((lane >> 4) * 8) * 2;
            {
                uint32_t r4[4];
                ldsm4t(sBq + bro + (uint32_t)(wn * 16) * 2, r4);
                bq[0][0] = r4[0]; bq[0][1] = r4[1];
                bq[1][0] = r4[2]; bq[1][1] = r4[3];
                ldsm4t(sBt + bro + (uint32_t)(wn * 16) * 2, r4);
                bt[0][0] = r4[0]; bt[0][1] = r4[1];
                bt[1][0] = r4[2]; bt[1][1] = r4[3];
            }
#pragma unroll
            for (int mf = 0; mf < 2; mf++)
#pragma unroll
                for (int nf = 0; nf < 2; nf++) {
                    mmah(accA[mf][nf], ah[mf], bq[nf]);
                    mmah(accB[mf][nf], ah[mf], bt[nf]);
                }
        }

        // stage scaled accumulators (fp16) — epA reuses E region
        __syncthreads();
#pragma unroll
        for (int mf = 0; mf < 2; mf++) {
            int r0 = wm * 32 + mf * 16 + g;
            float ri0 = g_rowinv[b * LC + c0 + r0], ri1 = g_rowinv[b * LC + c0 + r0 + 8];
#pragma unroll
            for (int nf = 0; nf < 2; nf++) {
                int d = wn * 16 + nf * 8 + tig * 2;
                *(uint32_t*)(epA + (r0 * EPH2 + d) * 2) = h2pk(accA[mf][nf][0] * ri0, accA[mf][nf][1] * ri0);
                *(uint32_t*)(epA + ((r0 + 8) * EPH2 + d) * 2) = h2pk(accA[mf][nf][2] * ri1, accA[mf][nf][3] * ri1);
                *(uint32_t*)(epB + (r0 * EPH2 + d) * 2) = h2pk(accB[mf][nf][0] * ri0, accB[mf][nf][1] * ri0);
                *(uint32_t*)(epB + ((r0 + 8) * EPH2 + d) * 2) = h2pk(accB[mf][nf][2] * ri1, accB[mf][nf][3] * ri1);
            }
        }
        __syncthreads();

        // seg0/1/2 stores (read epA); row = it*8+wid, lane -> d = lane*2 (256B/warp)
#pragma unroll
        for (int it = 0; it < 8; it++) {
            int row = it * 8 + wid;
            int d = lane * 2;
            uint32_t ua = *(uint32_t*)(epA + (row * EPH2 + d) * 2);
            float2 a01 = __half22float2(*(__half2*)&ua);
            float2 cv = __ldcs((const float2*)(Cp + ((size_t)(b * LC + c0 + row)) * DD + d0 + d));
            float* ob = out + ((size_t)(b * LC + c0 + row)) * (4 * DD) + d0 + d;
            __stcs((float2*)(ob), cv);
            __stcs((float2*)(ob + DD), a01);
            __stcs((float2*)(ob + 2 * DD), make_float2(cv.x * a01.x, cv.y * a01.y));
        }
        __syncthreads();   // epA reads done -> E region free for prefetch

        if (t + 1 < 4) stageE(ct + 1);   // overlap with seg3 stores below

        // seg3 stores (read epB annex — untouched by E prefetch)
#pragma unroll
        for (int it = 0; it < 8; it++) {
            int row = it * 8 + wid;
            int d = lane * 2;
            uint32_t ub = *(uint32_t*)(epB + (row * EPH2 + d) * 2);
            float2 b01 = __half22float2(*(__half2*)&ub);
            float2 cv = __ldcs((const float2*)(Cp + ((size_t)(b * LC + c0 + row)) * DD + d0 + d));
            float* ob = out + ((size_t)(b * LC + c0 + row)) * (4 * DD) + d0 + d;
            __stcs((float2*)(ob + 3 * DD), make_float2(cv.x * b01.x, cv.y * b01.y));
        }
    }
}

extern "C" void kernel_launch(void* const* d_in, const int* in_sizes, int n_in,
                              void* d_out, int out_size) {
    const float* C = (const float*)d_in[0];
    const float* Q = (const float*)d_in[1];
    const int* cmask = (const int*)d_in[2];
    const int* qmask = (const int*)d_in[3];
    const float* Ww = (const float*)d_in[4];
    const float* Wb = (const float*)d_in[5];
    float* out = (float*)d_out;

    static bool attr_set = false;
    if (!attr_set) {
        cudaFuncSetAttribute(k1_mma, cudaFuncAttributeMaxDynamicSharedMemorySize, SM_K1);
        cudaFuncSetAttribute(k2_mma, cudaFuncAttributeMaxDynamicSharedMemorySize, SM_K2);
        cudaFuncSetAttribute(k3_mma, cudaFuncAttributeMaxDynamicSharedMemorySize, SM_K3);
        attr_set = true;
    }

    k_prep<<<4608, 256>>>(C, Q, Ww, Wb);
    k1_mma<<<dim3(16, BB), 256, SM_K1>>>(cmask, qmask);
    k2_mma<<<dim3(8, BB), 256, SM_K2>>>(cmask);
    k3_mma<<<512, 256, SM_K3>>>(C, qmask, out);
}